// round 1
// baseline (speedup 1.0000x reference)
#include <cuda_runtime.h>

// Problem constants (from reference): N=16, M=100, LOC_MAX=10000, EMB=128, D=4
#define N_    16
#define M_    100
#define LOC_  10000
#define EMB_  128
#define TL    256   // l-tile per block == threads per block

// ---- packed f32x2 helpers (FFMA2 only reachable via PTX) ----
__device__ __forceinline__ unsigned long long pack2(float lo, float hi) {
    unsigned long long r;
    asm("mov.b64 %0, {%1, %2};" : "=l"(r) : "f"(lo), "f"(hi));
    return r;
}
__device__ __forceinline__ void unpack2(unsigned long long v, float& lo, float& hi) {
    asm("mov.b64 {%0, %1}, %2;" : "=f"(lo), "=f"(hi) : "l"(v));
}
__device__ __forceinline__ unsigned long long fma2(unsigned long long a,
                                                   unsigned long long b,
                                                   unsigned long long c) {
    unsigned long long d;
    asm("fma.rn.f32x2 %0, %1, %2, %3;" : "=l"(d) : "l"(a), "l"(b), "l"(c));
    return d;
}

// Dynamic smem: q[n,m,d] * w[m], M_*EMB_ floats = 51200 bytes
extern __shared__ float q_smem[];

__global__ __launch_bounds__(TL, 1)
void attn_fused_kernel(const float*  __restrict__ self_attn,   // (N, M, EMB)
                       const float4* __restrict__ delta4,      // (N, M, LOC, 4) as float4
                       const float*  __restrict__ emb_table,   // (LOC+1, EMB)
                       const float*  __restrict__ value_w,     // (M,)
                       float*        __restrict__ out)         // (N, LOC)
{
    const int n = blockIdx.y;
    const int l = blockIdx.x * TL + threadIdx.x;

    // Stage q[n] * w into shared memory (w folded in once).
    const float* qg = self_attn + (size_t)n * (M_ * EMB_);
    for (int idx = threadIdx.x; idx < M_ * EMB_; idx += TL) {
        int m = idx >> 7;            // idx / EMB_
        q_smem[idx] = qg[idx] * value_w[m];
    }
    __syncthreads();

    if (l >= LOC_) return;

    // h[d] accumulators: 128 floats as 64 packed f32x2 registers.
    unsigned long long h[64];
#pragma unroll
    for (int k = 0; k < 64; ++k) h[k] = 0ULL;

    // delta pointer for this (n, l); per-m stride is LOC_ float4s. Coalesced:
    // lane-consecutive l -> consecutive 16B.
    const float4* dp = delta4 + (size_t)n * (M_ * LOC_) + l;

    // depth-2 prefetch pipeline to cover ~400-600cyc DRAM latency
    float4 c0 = dp[0];
    float4 c1 = dp[LOC_];

    const ulonglong2* q2 = (const ulonglong2*)q_smem;   // [M_][32] of 16B

    for (int m = 0; m < M_; ++m) {
        float4 c2;
        if (m + 2 < M_) c2 = dp[(m + 2) * LOC_];
        else            c2 = make_float4(0.f, 0.f, 0.f, 0.f);

        float s = (c0.x + c0.y) + (c0.z + c0.w);        // sum over D
        unsigned long long s2 = pack2(s, s);

        const ulonglong2* qr = q2 + m * 32;             // broadcast LDS.128 row
#pragma unroll
        for (int k = 0; k < 32; ++k) {
            ulonglong2 v = qr[k];
            h[2 * k]     = fma2(s2, v.x, h[2 * k]);
            h[2 * k + 1] = fma2(s2, v.y, h[2 * k + 1]);
        }
        c0 = c1;
        c1 = c2;
    }

    // Epilogue: out[n,l] = emb_table[l+1] . h   (128-elem dot, packed)
    const ulonglong2* e2 = (const ulonglong2*)(emb_table + (size_t)(l + 1) * EMB_);
    unsigned long long acc0 = 0, acc1 = 0, acc2 = 0, acc3 = 0;
#pragma unroll
    for (int k = 0; k < 32; k += 2) {
        ulonglong2 u0 = e2[k];
        acc0 = fma2(u0.x, h[2 * k],     acc0);
        acc1 = fma2(u0.y, h[2 * k + 1], acc1);
        ulonglong2 u1 = e2[k + 1];
        acc2 = fma2(u1.x, h[2 * k + 2], acc2);
        acc3 = fma2(u1.y, h[2 * k + 3], acc3);
    }
    float a, b, r = 0.f;
    unpack2(acc0, a, b); r += a + b;
    unpack2(acc1, a, b); r += a + b;
    unpack2(acc2, a, b); r += a + b;
    unpack2(acc3, a, b); r += a + b;

    out[(size_t)n * LOC_ + l] = r;
}

extern "C" void kernel_launch(void* const* d_in, const int* in_sizes, int n_in,
                              void* d_out, int out_size)
{
    // metadata order: self_attn, self_delta, traj_len(unused), emb_table, value_w
    const float*  self_attn = (const float*) d_in[0];
    const float4* delta4    = (const float4*)d_in[1];
    const float*  emb_table = (const float*) d_in[3];
    const float*  value_w   = (const float*) d_in[4];
    float* out = (float*)d_out;

    const int smem_bytes = M_ * EMB_ * (int)sizeof(float);   // 51200 > 48KB default
    cudaFuncSetAttribute(attn_fused_kernel,
                         cudaFuncAttributeMaxDynamicSharedMemorySize, smem_bytes);

    dim3 grid((LOC_ + TL - 1) / TL, N_);
    attn_fused_kernel<<<grid, TL, smem_bytes>>>(self_attn, delta4, emb_table,
                                                value_w, out);
}

// round 2
// speedup vs baseline: 2.4540x; 2.4540x over previous
#include <cuda_runtime.h>

// Problem constants: N=16, M=100, LOC_MAX=10000, EMB=128, D=4
#define N_      16
#define M_      100
#define LOC_    10000
#define EMB_    128
#define TL      128     // l-tile per block
#define THREADS 256
#define MC      10      // m-chunk
#define NC      10      // M_/MC
#define LPT     5       // (MC*TL)/THREADS float4 loads per thread per chunk

// ---- packed f32x2 helpers ----
typedef unsigned long long ull;
__device__ __forceinline__ ull pack2(float lo, float hi) {
    ull r; asm("mov.b64 %0, {%1, %2};" : "=l"(r) : "f"(lo), "f"(hi)); return r;
}
__device__ __forceinline__ void unpack2(ull v, float& lo, float& hi) {
    asm("mov.b64 {%0, %1}, %2;" : "=f"(lo), "=f"(hi) : "l"(v));
}
__device__ __forceinline__ ull fma2(ull a, ull b, ull c) {
    ull d; asm("fma.rn.f32x2 %0, %1, %2, %3;" : "=l"(d) : "l"(a), "l"(b), "l"(c));
    return d;
}

// dynamic smem layout:
//   float q_s[M_*EMB_]   : 51200 B   (q[n,m,:] * w[m])
//   float s_s[MC*TL]     :  5120 B   (sum_d delta for current m-chunk)
//   float red[8*TL]      :  4096 B   (epilogue cross-warp reduction)
#define SMEM_Q    0
#define SMEM_S    (M_ * EMB_)
#define SMEM_RED  (M_ * EMB_ + MC * TL)
#define SMEM_FLOATS (M_ * EMB_ + MC * TL + 8 * TL)

extern __shared__ float smem[];

__global__ __launch_bounds__(THREADS, 2)
void attn_tiled_kernel(const float*  __restrict__ self_attn,   // (N, M, EMB)
                       const float4* __restrict__ delta4,      // (N, M, LOC, 4)
                       const float*  __restrict__ emb_table,   // (LOC+1, EMB)
                       const float*  __restrict__ value_w,     // (M,)
                       float*        __restrict__ out)         // (N, LOC)
{
    const int tid = threadIdx.x;
    const int n   = blockIdx.y;
    const int l0  = blockIdx.x * TL;

    float* q_s = smem + SMEM_Q;
    float* s_s = smem + SMEM_S;
    float* red = smem + SMEM_RED;

    // ---- stage q[n]*w into smem (vectorized) ----
    {
        const float4* qg4 = (const float4*)(self_attn + (size_t)n * (M_ * EMB_));
        float4*       qs4 = (float4*)q_s;
        for (int idx = tid; idx < (M_ * EMB_) / 4; idx += THREADS) {
            float w  = value_w[idx >> 5];       // (idx*4)/EMB_
            float4 v = qg4[idx];
            v.x *= w; v.y *= w; v.z *= w; v.w *= w;
            qs4[idx] = v;
        }
    }

    // ---- prefetch delta chunk 0 into registers ----
    const float4* dbase = delta4 + (size_t)n * (M_ * LOC_);
    float4 pre[LPT];
#pragma unroll
    for (int i = 0; i < LPT; ++i) {
        int idx = tid + i * THREADS;
        int ml = idx >> 7, l = idx & (TL - 1);
        int lg = l0 + l;
        pre[i] = (lg < LOC_) ? dbase[(size_t)ml * LOC_ + lg]
                             : make_float4(0.f, 0.f, 0.f, 0.f);
    }

    // ---- accumulators: h[j over 4 l's][kk over 8 packed-e] ----
    const int lt = tid & 31;        // lane: l = lt + 32*j
    const int et = tid >> 5;        // warp: e-range = et*16 .. et*16+15
    ull h[4][8];
#pragma unroll
    for (int j = 0; j < 4; ++j)
#pragma unroll
        for (int k = 0; k < 8; ++k) h[j][k] = 0ULL;

    // ---- main pipeline over m-chunks ----
    for (int c = 0; c < NC; ++c) {
        // reduce prefetched delta over D
        float sv[LPT];
#pragma unroll
        for (int i = 0; i < LPT; ++i)
            sv[i] = (pre[i].x + pre[i].y) + (pre[i].z + pre[i].w);

        __syncthreads();            // previous chunk's compute done
#pragma unroll
        for (int i = 0; i < LPT; ++i)
            s_s[tid + i * THREADS] = sv[i];     // layout [m_local][l]

        // issue next chunk's LDGs (latency overlapped by compute below)
        if (c + 1 < NC) {
            const float4* dch = dbase + (size_t)(c + 1) * MC * LOC_;
#pragma unroll
            for (int i = 0; i < LPT; ++i) {
                int idx = tid + i * THREADS;
                int ml = idx >> 7, l = idx & (TL - 1);
                int lg = l0 + l;
                pre[i] = (lg < LOC_) ? dch[(size_t)ml * LOC_ + lg]
                                     : make_float4(0.f, 0.f, 0.f, 0.f);
            }
        }
        __syncthreads();            // s_s (and q_s first time) visible

        // compute: for each m in chunk, rank-1 update of h
        const int m0 = c * MC;
#pragma unroll
        for (int mm = 0; mm < MC; ++mm) {
            float s0 = s_s[mm * TL + lt];
            float s1 = s_s[mm * TL + lt + 32];
            float s2 = s_s[mm * TL + lt + 64];
            float s3 = s_s[mm * TL + lt + 96];
            ull sp0 = pack2(s0, s0), sp1 = pack2(s1, s1);
            ull sp2 = pack2(s2, s2), sp3 = pack2(s3, s3);

            const ulonglong2* qr =
                (const ulonglong2*)(q_s + (m0 + mm) * EMB_ + et * 16);
#pragma unroll
            for (int k = 0; k < 4; ++k) {       // 4 x 16B = 16 emb floats
                ulonglong2 v = qr[k];           // broadcast LDS.128
                h[0][2*k]   = fma2(sp0, v.x, h[0][2*k]);
                h[0][2*k+1] = fma2(sp0, v.y, h[0][2*k+1]);
                h[1][2*k]   = fma2(sp1, v.x, h[1][2*k]);
                h[1][2*k+1] = fma2(sp1, v.y, h[1][2*k+1]);
                h[2][2*k]   = fma2(sp2, v.x, h[2][2*k]);
                h[2][2*k+1] = fma2(sp2, v.y, h[2][2*k+1]);
                h[3][2*k]   = fma2(sp3, v.x, h[3][2*k]);
                h[3][2*k+1] = fma2(sp3, v.y, h[3][2*k+1]);
            }
        }
    }

    // ---- epilogue: partial dot with emb row, then cross-warp reduce ----
#pragma unroll
    for (int j = 0; j < 4; ++j) {
        int l  = lt + 32 * j;
        int lg = l0 + l;
        float part = 0.f;
        if (lg < LOC_) {
            const float4* e4 =
                (const float4*)(emb_table + (size_t)(lg + 1) * EMB_) + et * 4;
#pragma unroll
            for (int k = 0; k < 4; ++k) {
                float4 ev = e4[k];
                float a, b;
                unpack2(h[j][2*k], a, b);
                part = fmaf(ev.x, a, part);
                part = fmaf(ev.y, b, part);
                unpack2(h[j][2*k+1], a, b);
                part = fmaf(ev.z, a, part);
                part = fmaf(ev.w, b, part);
            }
        }
        red[et * TL + l] = part;
    }
    __syncthreads();

    if (tid < TL) {
        int lg = l0 + tid;
        if (lg < LOC_) {
            float r = 0.f;
#pragma unroll
            for (int e = 0; e < 8; ++e) r += red[e * TL + tid];
            out[(size_t)n * LOC_ + lg] = r;
        }
    }
}

extern "C" void kernel_launch(void* const* d_in, const int* in_sizes, int n_in,
                              void* d_out, int out_size)
{
    // metadata order: self_attn, self_delta, traj_len(unused), emb_table, value_w
    const float*  self_attn = (const float*) d_in[0];
    const float4* delta4    = (const float4*)d_in[1];
    const float*  emb_table = (const float*) d_in[3];
    const float*  value_w   = (const float*) d_in[4];
    float* out = (float*)d_out;

    const int smem_bytes = SMEM_FLOATS * (int)sizeof(float);   // 60416 B
    cudaFuncSetAttribute(attn_tiled_kernel,
                         cudaFuncAttributeMaxDynamicSharedMemorySize, smem_bytes);

    dim3 grid((LOC_ + TL - 1) / TL, N_);
    attn_tiled_kernel<<<grid, THREADS, smem_bytes>>>(self_attn, delta4,
                                                     emb_table, value_w, out);
}